// round 5
// baseline (speedup 1.0000x reference)
#include <cuda_runtime.h>
#include <cuda_fp16.h>

#define NN 100000
#define F_IN 256
#define CH 16
#define CH2 8
#define NL 7

// ---------------- scratch (static device memory; no allocs) ----------------
__device__ __align__(128) __half g_hs_h[NN * CH];  // layer1 transform, fp16 (gather feed)
__device__ __align__(128) float g_out1[NN * CH];   // layer1 accumulator (fp32)
__device__ __align__(128) float g_hs2 [NN * CH2];  // layer2 pre-scaled transform (padded)
__device__ __align__(128) float g_out2[NN * CH2];  // layer2 accumulator (padded)
__device__ float g_dinv[NN];
__device__ int   g_deg [NN];

// vector float4 reduction (no return): red.global.add.v4.f32
__device__ __forceinline__ void red_add_f32x4(float* p, float a, float b, float c, float d) {
    asm volatile("red.global.add.v4.f32 [%0], {%1, %2, %3, %4};"
                 :: "l"(p), "f"(a), "f"(b), "f"(c), "f"(d) : "memory");
}

// packed dual fp32 FMA (sm_100a+): d.lo += a.lo*b.lo ; d.hi += a.hi*b.hi
__device__ __forceinline__ void ffma2(unsigned long long& d,
                                      unsigned long long a,
                                      unsigned long long b) {
    asm("fma.rn.f32x2 %0, %1, %2, %0;" : "+l"(d) : "l"(a), "l"(b));
}
__device__ __forceinline__ float f32x2_sum(unsigned long long v) {
    float lo = __uint_as_float((unsigned int)(v & 0xffffffffull));
    float hi = __uint_as_float((unsigned int)(v >> 32));
    return lo + hi;
}

// ---------------- degree / norm ----------------
__global__ void k_init_deg() {
    int i = blockIdx.x * blockDim.x + threadIdx.x;
    if (i < NN) g_deg[i] = 1;   // self loop
}

__global__ void k_deg(const int* __restrict__ dst, int E) {
    int i = blockIdx.x * blockDim.x + threadIdx.x;
    if (i < E) atomicAdd(&g_deg[dst[i]], 1);
}

__global__ void k_dinv() {
    int i = blockIdx.x * blockDim.x + threadIdx.x;
    if (i < NN) g_dinv[i] = rsqrtf((float)g_deg[i]);
}

// ---------------- GEMM1: out1 = hs = (x @ W0) * dinv ----------------
// 128 threads, tile TR=256 rows, k-chunk 16, software-pipelined global loads.
// Lane map: rl = lane&7 (row lane), cs = lane>>3 (col set, 4 cols each).
//   -> x smem reads broadcast across the 4 col-sets (same address);
//   -> W packed as k-pair u64 [128kp][16cols]: 4 cols = 2 LDS.128, 4 distinct addrs.
// Thread tile: 8 rows (rl + 8c, c=0..7, within warp's 64-row strip) x 4 cols.
// Per k-pair: 32 FFMA2, 8 LDS.64(x, broadcast) + 2 LDS.128(w)  => FMA-bound.
#define TR 256
#define KCH 16
__global__ void __launch_bounds__(128) k_gemm1(const float* __restrict__ x,
                                               const float* __restrict__ W0) {
    __shared__ float xs[TR * 20];     // stride 20 floats: 16B-aligned rows, conflict-free
    __shared__ float Wp[128 * 32];    // [kp][col] packed pairs: 2j=lo(k even), 2j+1=hi(k odd)
    const int tid  = threadIdx.x;
    const int lane = tid & 31;
    const int warp = tid >> 5;
    const int rl   = lane & 7;
    const int cs   = lane >> 3;
    const int row0 = blockIdx.x * TR;
    const int rbase = warp * 64 + rl;

    // stage W0 packed: Wp[(k>>1)*32 + 2*j + (k&1)] = W0[k*16+j]
    #pragma unroll
    for (int i = 0; i < 32; i++) {
        int idx = tid + 128 * i;
        int k = idx >> 4;
        int j = idx & 15;
        Wp[(k >> 1) * 32 + 2 * j + (k & 1)] = W0[idx];
    }

    unsigned long long acc[8][4];
    #pragma unroll
    for (int c = 0; c < 8; c++)
        #pragma unroll
        for (int j = 0; j < 4; j++) acc[c][j] = 0ull;

    float4 pre[8];
    // prologue: load chunk 0
    #pragma unroll
    for (int i = 0; i < 8; i++) {
        int f = tid + 128 * i;
        int r = f >> 2, q = f & 3;
        int grow = row0 + r;
        pre[i] = (grow < NN) ? *(const float4*)(x + (size_t)grow * F_IN + 4 * q)
                             : make_float4(0.f, 0.f, 0.f, 0.f);
    }

    for (int ch = 0; ch < F_IN / KCH; ch++) {
        const int kc = ch * KCH;
        __syncthreads();
        // store prefetched chunk
        #pragma unroll
        for (int i = 0; i < 8; i++) {
            int f = tid + 128 * i;
            int r = f >> 2, q = f & 3;
            *(float4*)(xs + r * 20 + 4 * q) = pre[i];
        }
        __syncthreads();
        // issue next chunk's global loads (latency hidden under compute)
        if (ch + 1 < F_IN / KCH) {
            #pragma unroll
            for (int i = 0; i < 8; i++) {
                int f = tid + 128 * i;
                int r = f >> 2, q = f & 3;
                int grow = row0 + r;
                pre[i] = (grow < NN)
                    ? *(const float4*)(x + (size_t)grow * F_IN + kc + KCH + 4 * q)
                    : make_float4(0.f, 0.f, 0.f, 0.f);
            }
        }
        // compute 8 k-pairs
        #pragma unroll
        for (int kpl = 0; kpl < KCH / 2; kpl++) {
            const float* wp = Wp + ((kc >> 1) + kpl) * 32 + 8 * cs;
            ulonglong2 wA = *(const ulonglong2*)wp;        // cols 4cs, 4cs+1
            ulonglong2 wB = *(const ulonglong2*)(wp + 4);  // cols 4cs+2, 4cs+3
            #pragma unroll
            for (int c = 0; c < 8; c++) {
                unsigned long long xv =
                    *(const unsigned long long*)(xs + (rbase + 8 * c) * 20 + 2 * kpl);
                ffma2(acc[c][0], xv, wA.x);
                ffma2(acc[c][1], xv, wA.y);
                ffma2(acc[c][2], xv, wB.x);
                ffma2(acc[c][3], xv, wB.y);
            }
        }
    }

    // epilogue: v = acc * dinv; write out1 (fp32, self-loop init) + hs fp16
    #pragma unroll
    for (int c = 0; c < 8; c++) {
        int grow = row0 + rbase + 8 * c;
        if (grow < NN) {
            float di = g_dinv[grow];
            float v0 = f32x2_sum(acc[c][0]) * di;
            float v1 = f32x2_sum(acc[c][1]) * di;
            float v2 = f32x2_sum(acc[c][2]) * di;
            float v3 = f32x2_sum(acc[c][3]) * di;
            *(float4*)(g_out1 + (size_t)grow * CH + 4 * cs) = make_float4(v0, v1, v2, v3);
            __half2 a = __floats2half2_rn(v0, v1);
            __half2 b = __floats2half2_rn(v2, v3);
            uint2 u;
            u.x = *(unsigned int*)&a;
            u.y = *(unsigned int*)&b;
            ((uint2*)g_hs_h)[(size_t)grow * 4 + cs] = u;
        }
    }
}

// ---------------- edge scatter, layer 1 (fp16 gather, fp32 scatter) ----------------
__global__ void k_edge1(const int* __restrict__ src, const int* __restrict__ dst, int E) {
    int t = blockIdx.x * blockDim.x + threadIdx.x;
    if (t >= 4 * E) return;
    int e = t >> 2;
    int c = t & 3;
    int s = src[e];
    int d = dst[e];
    uint2 u = ((const uint2*)g_hs_h)[(size_t)s * 4 + c];
    __half2 a = *reinterpret_cast<__half2*>(&u.x);
    __half2 b = *reinterpret_cast<__half2*>(&u.y);
    float2 f0 = __half22float2(a);
    float2 f1 = __half22float2(b);
    red_add_f32x4(g_out1 + (size_t)d * CH + 4 * c, f0.x, f0.y, f1.x, f1.y);
}

// ---------------- mid: h1 = relu(out1*dinv); hs2 = (h1 @ W1)*dinv; init out2 ----------
__global__ void __launch_bounds__(256) k_mid(const float* __restrict__ W1) {
    __shared__ float W1s[CH * NL];
    if (threadIdx.x < CH * NL) W1s[threadIdx.x] = W1[threadIdx.x];
    __syncthreads();

    int t = blockIdx.x * blockDim.x + threadIdx.x;
    int row0 = t * 4;
    if (row0 >= NN) return;   // NN divisible by 4

    float h[4][CH];
    float di[4];
    #pragma unroll
    for (int r = 0; r < 4; r++) {
        int row = row0 + r;
        di[r] = g_dinv[row];
        #pragma unroll
        for (int q = 0; q < 4; q++) {
            float4 v = *(const float4*)(g_out1 + (size_t)row * CH + q * 4);
            h[r][q * 4 + 0] = fmaxf(v.x * di[r], 0.f);
            h[r][q * 4 + 1] = fmaxf(v.y * di[r], 0.f);
            h[r][q * 4 + 2] = fmaxf(v.z * di[r], 0.f);
            h[r][q * 4 + 3] = fmaxf(v.w * di[r], 0.f);
        }
    }

    float acc[4][NL];
    #pragma unroll
    for (int r = 0; r < 4; r++)
        #pragma unroll
        for (int c = 0; c < NL; c++) acc[r][c] = 0.f;

    #pragma unroll
    for (int jj = 0; jj < CH; jj++) {
        #pragma unroll
        for (int c = 0; c < NL; c++) {
            float w = W1s[jj * NL + c];
            #pragma unroll
            for (int r = 0; r < 4; r++) acc[r][c] += h[r][jj] * w;
        }
    }

    #pragma unroll
    for (int r = 0; r < 4; r++) {
        int row = row0 + r;
        float4 lo = make_float4(acc[r][0] * di[r], acc[r][1] * di[r],
                                acc[r][2] * di[r], acc[r][3] * di[r]);
        float4 hi = make_float4(acc[r][4] * di[r], acc[r][5] * di[r],
                                acc[r][6] * di[r], 0.f);
        *(float4*)(g_hs2  + (size_t)row * CH2)     = lo;
        *(float4*)(g_hs2  + (size_t)row * CH2 + 4) = hi;
        *(float4*)(g_out2 + (size_t)row * CH2)     = lo;   // self loop
        *(float4*)(g_out2 + (size_t)row * CH2 + 4) = hi;
    }
}

// ---------------- edge scatter, layer 2 (8 floats/row padded, 2 threads/edge) ----------
__global__ void k_edge2(const int* __restrict__ src, const int* __restrict__ dst, int E) {
    int t = blockIdx.x * blockDim.x + threadIdx.x;
    if (t >= 2 * E) return;
    int e = t >> 1;
    int c = t & 1;
    int s = src[e];
    int d = dst[e];
    float4 v = ((const float4*)(g_hs2 + (size_t)s * CH2))[c];
    red_add_f32x4((float*)(((float4*)(g_out2 + (size_t)d * CH2)) + c), v.x, v.y, v.z, v.w);
}

// ---------------- finalize: out = exp(out2*dinv) + 1 ----------------
__global__ void k_final(float* __restrict__ out) {
    int t = blockIdx.x * blockDim.x + threadIdx.x;
    if (t >= NN * NL) return;
    int i = t / NL;
    int j = t - i * NL;
    out[t] = expf(g_out2[(size_t)i * CH2 + j] * g_dinv[i]) + 1.0f;
}

// ---------------- launch ----------------
extern "C" void kernel_launch(void* const* d_in, const int* in_sizes, int n_in,
                              void* d_out, int out_size) {
    const float* x  = (const float*)d_in[0];
    const float* W0 = (const float*)d_in[1];
    const float* W1 = (const float*)d_in[2];
    const int*   ei = (const int*)d_in[3];
    const int E = in_sizes[3] / 2;
    const int* src = ei;
    const int* dst = ei + E;
    float* out = (float*)d_out;

    k_init_deg<<<(NN + 255) / 256, 256>>>();
    k_deg<<<(E + 255) / 256, 256>>>(dst, E);
    k_dinv<<<(NN + 255) / 256, 256>>>();

    k_gemm1<<<(NN + TR - 1) / TR, 128>>>(x, W0);

    k_edge1<<<(4 * E + 255) / 256, 256>>>(src, dst, E);

    k_mid<<<(NN / 4 + 255) / 256, 256>>>(W1);

    k_edge2<<<(2 * E + 255) / 256, 256>>>(src, dst, E);

    k_final<<<(NN * NL + 255) / 256, 256>>>(out);
}